// round 4
// baseline (speedup 1.0000x reference)
#include <cuda_runtime.h>

#define BB 32
#define LL 4096
#define HH 128
#define H2 256
#define VV 32000
#define TOK 64
#define NTOK (BB*LL)

// Scratch (static device globals: no allocation in kernel_launch)
__device__ float g_k[(size_t)NTOK * HH];   // NORMALIZED k (kn), (B*L, H)
__device__ float g_nrm[NTOK];              // norm_eff = max(||k||, 1e-12)
__device__ float g_read[BB * HH];          // M @ q
__device__ float g_r2[BB * HH];            // read @ Wrp + brp

// ---------------------------------------------------------------------------
// Kernel A: fused embed-gather -> MLP(relu) -> residual+LN -> k-projection
// One CTA = 64 tokens, 256 threads, 128 KB dynamic smem.
// ---------------------------------------------------------------------------
__global__ void __launch_bounds__(256) kA(
    const int* __restrict__ seq, const float* __restrict__ embed,
    const float* __restrict__ W1, const float* __restrict__ b1,
    const float* __restrict__ W2, const float* __restrict__ b2,
    const float* __restrict__ lng, const float* __restrict__ lnb,
    const float* __restrict__ Wkp)
{
    extern __shared__ float sm[];
    float* sH = sm;               // 64 x 128
    float* sW = sm + TOK * HH;    // weight staging (8192 floats)
    float* sA = sW + 8192;        // 64 x 256 (also reused as 64 x 128)
    __shared__ int sSeq[TOK];
    __shared__ float sInv[TOK];

    const int tid = threadIdx.x;
    const int t0  = blockIdx.x * TOK;
    if (tid < TOK) sSeq[tid] = seq[t0 + tid];
    __syncthreads();

    // gather embeddings (float4)
    {
        float4* d = (float4*)sH;
        const float4* e = (const float4*)embed;
        for (int idx = tid; idx < TOK * (HH / 4); idx += 256) {
            int r = idx >> 5;
            d[idx] = e[(size_t)sSeq[r] * (HH / 4) + (idx & 31)];
        }
    }
    __syncthreads();

    const int tx = tid & 15, ty = tid >> 4;

    // ---- GEMM1: A = relu(H @ W1 + b1)   (64x128x256)
    float acc[4][16];
#pragma unroll
    for (int r = 0; r < 4; r++)
#pragma unroll
        for (int c = 0; c < 16; c++) acc[r][c] = 0.f;

    for (int kb = 0; kb < 4; kb++) {
        __syncthreads();
        {
            float4* d = (float4*)sW;
            const float4* s = (const float4*)W1;
            for (int idx = tid; idx < 32 * (H2 / 4); idx += 256) {
                int r = idx >> 6;
                d[idx] = s[(kb * 32 + r) * (H2 / 4) + (idx & 63)];
            }
        }
        __syncthreads();
#pragma unroll
        for (int kk = 0; kk < 32; kk++) {
            float hv[4];
#pragma unroll
            for (int r = 0; r < 4; r++) hv[r] = sH[(ty * 4 + r) * HH + kb * 32 + kk];
#pragma unroll
            for (int q = 0; q < 4; q++) {
                float4 w = ((const float4*)sW)[kk * (H2 / 4) + q * 16 + tx];
#pragma unroll
                for (int r = 0; r < 4; r++) {
                    acc[r][q * 4 + 0] = fmaf(hv[r], w.x, acc[r][q * 4 + 0]);
                    acc[r][q * 4 + 1] = fmaf(hv[r], w.y, acc[r][q * 4 + 1]);
                    acc[r][q * 4 + 2] = fmaf(hv[r], w.z, acc[r][q * 4 + 2]);
                    acc[r][q * 4 + 3] = fmaf(hv[r], w.w, acc[r][q * 4 + 3]);
                }
            }
        }
    }
    // bias + relu -> sA (64 x 256). sA untouched during GEMM1.
#pragma unroll
    for (int q = 0; q < 4; q++)
#pragma unroll
        for (int u = 0; u < 4; u++) {
            int c = q * 64 + tx * 4 + u;
            float bb = b1[c];
#pragma unroll
            for (int r = 0; r < 4; r++) {
                float v = acc[r][q * 4 + u] + bb;
                sA[(ty * 4 + r) * H2 + c] = v > 0.f ? v : 0.f;
            }
        }

    // ---- GEMM2: F = A @ W2 + b2   (64x256x128)
    float acc2[4][8];
#pragma unroll
    for (int r = 0; r < 4; r++)
#pragma unroll
        for (int c = 0; c < 8; c++) acc2[r][c] = 0.f;

    for (int kb = 0; kb < 4; kb++) {
        __syncthreads();
        {
            float4* d = (float4*)sW;
            const float4* s = (const float4*)W2;
            for (int idx = tid; idx < 64 * (HH / 4); idx += 256) {
                int r = idx >> 5;
                d[idx] = s[(kb * 64 + r) * (HH / 4) + (idx & 31)];
            }
        }
        __syncthreads();
#pragma unroll
        for (int kk = 0; kk < 64; kk++) {
            float av[4];
#pragma unroll
            for (int r = 0; r < 4; r++) av[r] = sA[(ty * 4 + r) * H2 + kb * 64 + kk];
#pragma unroll
            for (int q = 0; q < 2; q++) {
                float4 w = ((const float4*)sW)[kk * (HH / 4) + q * 16 + tx];
#pragma unroll
                for (int r = 0; r < 4; r++) {
                    acc2[r][q * 4 + 0] = fmaf(av[r], w.x, acc2[r][q * 4 + 0]);
                    acc2[r][q * 4 + 1] = fmaf(av[r], w.y, acc2[r][q * 4 + 1]);
                    acc2[r][q * 4 + 2] = fmaf(av[r], w.z, acc2[r][q * 4 + 2]);
                    acc2[r][q * 4 + 3] = fmaf(av[r], w.w, acc2[r][q * 4 + 3]);
                }
            }
        }
    }
    __syncthreads();   // all sA reads done before overwrite

    // x = F + b2 + H -> sA (as 64 x 128)
#pragma unroll
    for (int q = 0; q < 2; q++)
#pragma unroll
        for (int u = 0; u < 4; u++) {
            int c = q * 64 + tx * 4 + u;
            float bb = b2[c];
#pragma unroll
            for (int r = 0; r < 4; r++) {
                int t = ty * 4 + r;
                sA[t * HH + c] = acc2[r][q * 4 + u] + bb + sH[t * HH + c];
            }
        }
    __syncthreads();

    // LayerNorm per token -> sH
    {
        int warp = tid >> 5, lane = tid & 31;
        for (int tt = warp * 8; tt < warp * 8 + 8; tt++) {
            float4 x = ((const float4*)sA)[tt * 32 + lane];
            float s1 = x.x + x.y + x.z + x.w;
            float s2 = fmaf(x.x, x.x, fmaf(x.y, x.y, fmaf(x.z, x.z, x.w * x.w)));
#pragma unroll
            for (int o = 16; o; o >>= 1) {
                s1 += __shfl_xor_sync(0xffffffffu, s1, o);
                s2 += __shfl_xor_sync(0xffffffffu, s2, o);
            }
            float mu  = s1 * (1.f / HH);
            float var = s2 * (1.f / HH) - mu * mu;
            float rs  = rsqrtf(var + 1e-5f);
            float4 gg = ((const float4*)lng)[lane];
            float4 bb = ((const float4*)lnb)[lane];
            float4 o;
            o.x = (x.x - mu) * rs * gg.x + bb.x;
            o.y = (x.y - mu) * rs * gg.y + bb.y;
            o.z = (x.z - mu) * rs * gg.z + bb.z;
            o.w = (x.w - mu) * rs * gg.w + bb.w;
            ((float4*)sH)[tt * 32 + lane] = o;
        }
    }
    __syncthreads();

    // ---- GEMM3: K = HN @ Wkp   (64x128x128)
    float acc3[4][8];
#pragma unroll
    for (int r = 0; r < 4; r++)
#pragma unroll
        for (int c = 0; c < 8; c++) acc3[r][c] = 0.f;

    for (int kb = 0; kb < 2; kb++) {
        __syncthreads();
        {
            float4* d = (float4*)sW;
            const float4* s = (const float4*)Wkp;
            for (int idx = tid; idx < 64 * (HH / 4); idx += 256) {
                int r = idx >> 5;
                d[idx] = s[(kb * 64 + r) * (HH / 4) + (idx & 31)];
            }
        }
        __syncthreads();
#pragma unroll
        for (int kk = 0; kk < 64; kk++) {
            float hv[4];
#pragma unroll
            for (int r = 0; r < 4; r++) hv[r] = sH[(ty * 4 + r) * HH + kb * 64 + kk];
#pragma unroll
            for (int q = 0; q < 2; q++) {
                float4 w = ((const float4*)sW)[kk * (HH / 4) + q * 16 + tx];
#pragma unroll
                for (int r = 0; r < 4; r++) {
                    acc3[r][q * 4 + 0] = fmaf(hv[r], w.x, acc3[r][q * 4 + 0]);
                    acc3[r][q * 4 + 1] = fmaf(hv[r], w.y, acc3[r][q * 4 + 1]);
                    acc3[r][q * 4 + 2] = fmaf(hv[r], w.z, acc3[r][q * 4 + 2]);
                    acc3[r][q * 4 + 3] = fmaf(hv[r], w.w, acc3[r][q * 4 + 3]);
                }
            }
        }
    }
    // write K into sA (64 x 128); sA is dead during GEMM3
#pragma unroll
    for (int q = 0; q < 2; q++)
#pragma unroll
        for (int u = 0; u < 4; u++) {
            int c = q * 64 + tx * 4 + u;
#pragma unroll
            for (int r = 0; r < 4; r++)
                sA[(ty * 4 + r) * HH + c] = acc3[r][q * 4 + u];
        }
    __syncthreads();

    // per-token norms: write norm_eff to global, 1/norm_eff to smem
    {
        int warp = tid >> 5, lane = tid & 31;
        for (int tt = warp * 8; tt < warp * 8 + 8; tt++) {
            float4 x = ((const float4*)sA)[tt * 32 + lane];
            float ss = fmaf(x.x, x.x, fmaf(x.y, x.y, fmaf(x.z, x.z, x.w * x.w)));
#pragma unroll
            for (int o = 16; o; o >>= 1) ss += __shfl_xor_sync(0xffffffffu, ss, o);
            if (lane == 0) {
                float n = fmaxf(sqrtf(ss), 1e-12f);
                g_nrm[t0 + tt] = n;
                sInv[tt] = 1.f / n;
            }
        }
    }
    __syncthreads();

    // write NORMALIZED kn to global: kn = k * (1/norm_eff)
    {
        float4* gk = (float4*)g_k;
        const float4* s = (const float4*)sA;
        for (int idx = tid; idx < TOK * 32; idx += 256) {
            float inv = sInv[idx >> 5];
            float4 v = s[idx];
            v.x *= inv; v.y *= inv; v.z *= inv; v.w *= inv;
            gk[(size_t)t0 * 32 + idx] = v;
        }
    }
}

// ---------------------------------------------------------------------------
// Kernel B: delta-rule scan, 4 rows per warp.
// Lane = g*8 + s: row group g (row R0+g), segment s (elements s*16..s*16+15).
// Each lane holds 16 M-elements (4 float4). Dot-product reduction is only
// 3 shuffles (within the 8-lane group). kn loads amortized over 4 rows.
// ---------------------------------------------------------------------------
__global__ void __launch_bounds__(256) kScan()
{
    const int warpId = threadIdx.x >> 5, lane = threadIdx.x & 31;
    const int w  = blockIdx.x * 8 + warpId;      // 0..1023
    const int b  = w >> 5;                        // batch
    const int R0 = (w & 31) << 2;                 // first of 4 rows
    const int g  = lane >> 3;                     // row group 0..3
    const int s  = lane & 7;                      // segment 0..7

    const float*  kbase = g_k + (size_t)b * LL * HH;
    const float4* kseg  = (const float4*)kbase + s * 4;   // +t*32 per step
    const float*  krow  = kbase + R0 + g;                  // kn[t][R0+g]
    const float*  np    = g_nrm + b * LL;

    float4 m0 = {0,0,0,0}, m1 = {0,0,0,0}, m2 = {0,0,0,0}, m3 = {0,0,0,0};

    // prologue: load step 0
    float4 c0 = __ldg(kseg + 0);
    float4 c1 = __ldg(kseg + 1);
    float4 c2 = __ldg(kseg + 2);
    float4 c3 = __ldg(kseg + 3);
    float  kni = __ldg(krow);
    float  nrm = __ldg(np);

    for (int t = 0; t < LL - 1; t++) {
        // prefetch t+1 (last prefetch = q row)
        const float4* nk = kseg + (t + 1) * 32;
        float4 n0 = __ldg(nk + 0);
        float4 n1 = __ldg(nk + 1);
        float4 n2 = __ldg(nk + 2);
        float4 n3 = __ldg(nk + 3);
        float  kni_n = __ldg(krow + (size_t)(t + 1) * HH);
        float  nrm_n = __ldg(np + t + 1);

        // partial dot over this lane's 16 elements (4 independent chains)
        float pa = fmaf(m0.x, c0.x, fmaf(m0.y, c0.y, fmaf(m0.z, c0.z, m0.w * c0.w)));
        float pb = fmaf(m1.x, c1.x, fmaf(m1.y, c1.y, fmaf(m1.z, c1.z, m1.w * c1.w)));
        float pc = fmaf(m2.x, c2.x, fmaf(m2.y, c2.y, fmaf(m2.z, c2.z, m2.w * c2.w)));
        float pd = fmaf(m3.x, c3.x, fmaf(m3.y, c3.y, fmaf(m3.z, c3.z, m3.w * c3.w)));
        float p = (pa + pb) + (pc + pd);

        // reduce over the 8 lanes of this row group
        p += __shfl_xor_sync(0xffffffffu, p, 4);
        p += __shfl_xor_sync(0xffffffffu, p, 2);
        p += __shfl_xor_sync(0xffffffffu, p, 1);

        float c = fmaf(kni, nrm, -p);    // raw k_i - (M.kn)_i

        m0.x = fmaf(c, c0.x, m0.x); m0.y = fmaf(c, c0.y, m0.y);
        m0.z = fmaf(c, c0.z, m0.z); m0.w = fmaf(c, c0.w, m0.w);
        m1.x = fmaf(c, c1.x, m1.x); m1.y = fmaf(c, c1.y, m1.y);
        m1.z = fmaf(c, c1.z, m1.z); m1.w = fmaf(c, c1.w, m1.w);
        m2.x = fmaf(c, c2.x, m2.x); m2.y = fmaf(c, c2.y, m2.y);
        m2.z = fmaf(c, c2.z, m2.z); m2.w = fmaf(c, c2.w, m2.w);
        m3.x = fmaf(c, c3.x, m3.x); m3.y = fmaf(c, c3.y, m3.y);
        m3.z = fmaf(c, c3.z, m3.z); m3.w = fmaf(c, c3.w, m3.w);

        c0 = n0; c1 = n1; c2 = n2; c3 = n3; kni = kni_n; nrm = nrm_n;
    }

    // epilogue: q = kn[L-1] * nrm[L-1]  ->  read_i = nrm * (M . kn)
    float pa = fmaf(m0.x, c0.x, fmaf(m0.y, c0.y, fmaf(m0.z, c0.z, m0.w * c0.w)));
    float pb = fmaf(m1.x, c1.x, fmaf(m1.y, c1.y, fmaf(m1.z, c1.z, m1.w * c1.w)));
    float pc = fmaf(m2.x, c2.x, fmaf(m2.y, c2.y, fmaf(m2.z, c2.z, m2.w * c2.w)));
    float pd = fmaf(m3.x, c3.x, fmaf(m3.y, c3.y, fmaf(m3.z, c3.z, m3.w * c3.w)));
    float p = (pa + pb) + (pc + pd);
    p += __shfl_xor_sync(0xffffffffu, p, 4);
    p += __shfl_xor_sync(0xffffffffu, p, 2);
    p += __shfl_xor_sync(0xffffffffu, p, 1);
    if (s == 0) g_read[b * HH + R0 + g] = p * nrm;
}

// ---------------------------------------------------------------------------
// Kernel C: r2 = read @ Wrp + brp   (32 x 128)
// ---------------------------------------------------------------------------
__global__ void __launch_bounds__(256) kC(const float* __restrict__ Wrp,
                                          const float* __restrict__ brp)
{
    int idx = blockIdx.x * 256 + threadIdx.x;
    if (idx >= BB * HH) return;
    int b = idx >> 7, d = idx & 127;
    float s = brp[d];
#pragma unroll 8
    for (int h = 0; h < HH; h++)
        s = fmaf(__ldg(&g_read[b * HH + h]), __ldg(&Wrp[h * HH + d]), s);
    g_r2[idx] = s;
}

// ---------------------------------------------------------------------------
// Kernel D: out = r2 @ Wout + bout   (32 x 32000). Thread per output column v.
// h-loop unrolled by 8 for MLP=8 (was MLP~1 -> 205 GB/s; now bandwidth-bound).
// ---------------------------------------------------------------------------
__global__ void __launch_bounds__(256) kD(const float* __restrict__ Wout,
                                          const float* __restrict__ bout,
                                          float* __restrict__ out)
{
    __shared__ float sr[BB * HH];
    for (int idx = threadIdx.x; idx < BB * HH; idx += 256) sr[idx] = g_r2[idx];
    __syncthreads();
    int v = blockIdx.x * 256 + threadIdx.x;
    if (v >= VV) return;

    float acc[BB];
#pragma unroll
    for (int b = 0; b < BB; b++) acc[b] = 0.f;

#pragma unroll 1
    for (int h0 = 0; h0 < HH; h0 += 8) {
        float wv[8];
#pragma unroll
        for (int u = 0; u < 8; u++)
            wv[u] = __ldg(&Wout[(size_t)(h0 + u) * VV + v]);
#pragma unroll
        for (int u = 0; u < 8; u++)
#pragma unroll
            for (int b = 0; b < BB; b++)
                acc[b] = fmaf(sr[b * HH + h0 + u], wv[u], acc[b]);
    }
    float bo = __ldg(&bout[v]);
#pragma unroll
    for (int b = 0; b < BB; b++)
        out[(size_t)b * VV + v] = acc[b] + bo;
}

// ---------------------------------------------------------------------------
extern "C" void kernel_launch(void* const* d_in, const int* in_sizes, int n_in,
                              void* d_out, int out_size)
{
    const int*   seq   = (const int*)d_in[0];
    const float* embed = (const float*)d_in[1];
    const float* W1    = (const float*)d_in[2];
    const float* b1    = (const float*)d_in[3];
    const float* W2    = (const float*)d_in[4];
    const float* b2    = (const float*)d_in[5];
    const float* lng   = (const float*)d_in[6];
    const float* lnb   = (const float*)d_in[7];
    const float* Wkp   = (const float*)d_in[8];
    const float* Wrp   = (const float*)d_in[9];
    const float* brp   = (const float*)d_in[10];
    const float* Wout  = (const float*)d_in[11];
    const float* bout  = (const float*)d_in[12];
    float* out = (float*)d_out;

    cudaFuncSetAttribute(kA, cudaFuncAttributeMaxDynamicSharedMemorySize, 131072);

    kA<<<NTOK / TOK, 256, 131072>>>(seq, embed, W1, b1, W2, b2, lng, lnb, Wkp);
    kScan<<<128, 256>>>();
    kC<<<(BB * HH + 255) / 256, 256>>>(Wrp, brp);
    kD<<<(VV + 255) / 256, 256>>>(Wout, bout, out);
}

// round 6
// speedup vs baseline: 1.4757x; 1.4757x over previous
#include <cuda_runtime.h>

typedef unsigned long long ull;

#define BB 32
#define LL 4096
#define HH 128
#define H2 256
#define VV 32000
#define TOK 64
#define NTOK (BB*LL)

// ---- packed-fp32 helpers (f32x2 is plain sm_100 PTX; exact IEEE fp32) ------
__device__ __forceinline__ ull pk2(float lo, float hi) {
    ull r; asm("mov.b64 %0, {%1, %2};" : "=l"(r) : "f"(lo), "f"(hi)); return r;
}
__device__ __forceinline__ void upk2(ull v, float& lo, float& hi) {
    asm("mov.b64 {%0, %1}, %2;" : "=f"(lo), "=f"(hi) : "l"(v));
}
__device__ __forceinline__ ull f2fma(ull a, ull b, ull c) {
    ull d; asm("fma.rn.f32x2 %0, %1, %2, %3;" : "=l"(d) : "l"(a), "l"(b), "l"(c)); return d;
}
__device__ __forceinline__ float wredux(float p) {
    p += __shfl_xor_sync(0xffffffffu, p, 16);
    p += __shfl_xor_sync(0xffffffffu, p, 8);
    p += __shfl_xor_sync(0xffffffffu, p, 4);
    p += __shfl_xor_sync(0xffffffffu, p, 2);
    p += __shfl_xor_sync(0xffffffffu, p, 1);
    return p;
}

// Scratch (static device globals: no allocation in kernel_launch)
__device__ float g_k[(size_t)NTOK * HH];   // NORMALIZED k (kn), (B*L, H)
__device__ float g_nrm[NTOK];              // norm_eff = max(||k||, 1e-12)
__device__ float g_read[BB * HH];          // M @ q
__device__ float g_r2[BB * HH];            // read @ Wrp + brp

// ---------------------------------------------------------------------------
// Kernel A: fused embed-gather -> MLP(relu) -> residual+LN -> k-projection
// One CTA = 64 tokens, 256 threads, 128 KB dynamic smem. f32x2 packed FMA.
// ---------------------------------------------------------------------------
__global__ void __launch_bounds__(256) kA(
    const int* __restrict__ seq, const float* __restrict__ embed,
    const float* __restrict__ W1, const float* __restrict__ b1,
    const float* __restrict__ W2, const float* __restrict__ b2,
    const float* __restrict__ lng, const float* __restrict__ lnb,
    const float* __restrict__ Wkp)
{
    extern __shared__ float sm[];
    float* sH = sm;               // 64 x 128
    float* sW = sm + TOK * HH;    // weight staging (8192 floats)
    float* sA = sW + 8192;        // 64 x 256 (also reused as 64 x 128)
    __shared__ int sSeq[TOK];
    __shared__ float sInv[TOK];

    const int tid = threadIdx.x;
    const int t0  = blockIdx.x * TOK;
    if (tid < TOK) sSeq[tid] = seq[t0 + tid];
    __syncthreads();

    // gather embeddings (float4)
    {
        float4* d = (float4*)sH;
        const float4* e = (const float4*)embed;
        for (int idx = tid; idx < TOK * (HH / 4); idx += 256) {
            int r = idx >> 5;
            d[idx] = e[(size_t)sSeq[r] * (HH / 4) + (idx & 31)];
        }
    }
    __syncthreads();

    const int tx = tid & 15, ty = tid >> 4;

    // ---- GEMM1: A = relu(H @ W1 + b1)   (64x128x256), packed f32x2
    ull accp[4][8];
#pragma unroll
    for (int r = 0; r < 4; r++)
#pragma unroll
        for (int c = 0; c < 8; c++) accp[r][c] = 0ULL;

    for (int kb = 0; kb < 4; kb++) {
        __syncthreads();
        {
            float4* d = (float4*)sW;
            const float4* s = (const float4*)W1;
            for (int idx = tid; idx < 32 * (H2 / 4); idx += 256) {
                int r = idx >> 6;
                d[idx] = s[(kb * 32 + r) * (H2 / 4) + (idx & 63)];
            }
        }
        __syncthreads();
#pragma unroll
        for (int kk = 0; kk < 32; kk++) {
            ull hd[4];
#pragma unroll
            for (int r = 0; r < 4; r++) {
                float hv = sH[(ty * 4 + r) * HH + kb * 32 + kk];
                hd[r] = pk2(hv, hv);
            }
#pragma unroll
            for (int q = 0; q < 4; q++) {
                ulonglong2 w = ((const ulonglong2*)sW)[kk * (H2 / 4) + q * 16 + tx];
#pragma unroll
                for (int r = 0; r < 4; r++) {
                    accp[r][q * 2 + 0] = f2fma(hd[r], w.x, accp[r][q * 2 + 0]);
                    accp[r][q * 2 + 1] = f2fma(hd[r], w.y, accp[r][q * 2 + 1]);
                }
            }
        }
    }
    // bias + relu -> sA (64 x 256). sA untouched during GEMM1.
#pragma unroll
    for (int q = 0; q < 4; q++)
#pragma unroll
        for (int h = 0; h < 2; h++) {
            int c = q * 64 + tx * 4 + h * 2;
            float bb0 = b1[c], bb1 = b1[c + 1];
#pragma unroll
            for (int r = 0; r < 4; r++) {
                float lo, hi; upk2(accp[r][q * 2 + h], lo, hi);
                float v0 = lo + bb0, v1 = hi + bb1;
                sA[(ty * 4 + r) * H2 + c]     = v0 > 0.f ? v0 : 0.f;
                sA[(ty * 4 + r) * H2 + c + 1] = v1 > 0.f ? v1 : 0.f;
            }
        }

    // ---- GEMM2: F = A @ W2 + b2   (64x256x128), packed
    ull accp2[4][4];
#pragma unroll
    for (int r = 0; r < 4; r++)
#pragma unroll
        for (int c = 0; c < 4; c++) accp2[r][c] = 0ULL;

    for (int kb = 0; kb < 4; kb++) {
        __syncthreads();
        {
            float4* d = (float4*)sW;
            const float4* s = (const float4*)W2;
            for (int idx = tid; idx < 64 * (HH / 4); idx += 256) {
                int r = idx >> 5;
                d[idx] = s[(kb * 64 + r) * (HH / 4) + (idx & 31)];
            }
        }
        __syncthreads();
#pragma unroll
        for (int kk = 0; kk < 64; kk++) {
            ull ad[4];
#pragma unroll
            for (int r = 0; r < 4; r++) {
                float av = sA[(ty * 4 + r) * H2 + kb * 64 + kk];
                ad[r] = pk2(av, av);
            }
#pragma unroll
            for (int q = 0; q < 2; q++) {
                ulonglong2 w = ((const ulonglong2*)sW)[kk * (HH / 4) + q * 16 + tx];
#pragma unroll
                for (int r = 0; r < 4; r++) {
                    accp2[r][q * 2 + 0] = f2fma(ad[r], w.x, accp2[r][q * 2 + 0]);
                    accp2[r][q * 2 + 1] = f2fma(ad[r], w.y, accp2[r][q * 2 + 1]);
                }
            }
        }
    }
    __syncthreads();   // all sA reads done before overwrite

    // x = F + b2 + H -> sA (as 64 x 128)
#pragma unroll
    for (int q = 0; q < 2; q++)
#pragma unroll
        for (int h = 0; h < 2; h++) {
            int c = q * 64 + tx * 4 + h * 2;
            float bb0 = b2[c], bb1 = b2[c + 1];
#pragma unroll
            for (int r = 0; r < 4; r++) {
                int t = ty * 4 + r;
                float lo, hi; upk2(accp2[r][q * 2 + h], lo, hi);
                sA[t * HH + c]     = lo + bb0 + sH[t * HH + c];
                sA[t * HH + c + 1] = hi + bb1 + sH[t * HH + c + 1];
            }
        }
    __syncthreads();

    // LayerNorm per token -> sH
    {
        int warp = tid >> 5, lane = tid & 31;
        for (int tt = warp * 8; tt < warp * 8 + 8; tt++) {
            float4 x = ((const float4*)sA)[tt * 32 + lane];
            float s1 = x.x + x.y + x.z + x.w;
            float s2 = fmaf(x.x, x.x, fmaf(x.y, x.y, fmaf(x.z, x.z, x.w * x.w)));
#pragma unroll
            for (int o = 16; o; o >>= 1) {
                s1 += __shfl_xor_sync(0xffffffffu, s1, o);
                s2 += __shfl_xor_sync(0xffffffffu, s2, o);
            }
            float mu  = s1 * (1.f / HH);
            float var = s2 * (1.f / HH) - mu * mu;
            float rs  = rsqrtf(var + 1e-5f);
            float4 gg = ((const float4*)lng)[lane];
            float4 bb = ((const float4*)lnb)[lane];
            float4 o;
            o.x = (x.x - mu) * rs * gg.x + bb.x;
            o.y = (x.y - mu) * rs * gg.y + bb.y;
            o.z = (x.z - mu) * rs * gg.z + bb.z;
            o.w = (x.w - mu) * rs * gg.w + bb.w;
            ((float4*)sH)[tt * 32 + lane] = o;
        }
    }
    __syncthreads();

    // ---- GEMM3: K = HN @ Wkp   (64x128x128), packed
    ull accp3[4][4];
#pragma unroll
    for (int r = 0; r < 4; r++)
#pragma unroll
        for (int c = 0; c < 4; c++) accp3[r][c] = 0ULL;

    for (int kb = 0; kb < 2; kb++) {
        __syncthreads();
        {
            float4* d = (float4*)sW;
            const float4* s = (const float4*)Wkp;
            for (int idx = tid; idx < 64 * (HH / 4); idx += 256) {
                int r = idx >> 5;
                d[idx] = s[(kb * 64 + r) * (HH / 4) + (idx & 31)];
            }
        }
        __syncthreads();
#pragma unroll
        for (int kk = 0; kk < 64; kk++) {
            ull hd[4];
#pragma unroll
            for (int r = 0; r < 4; r++) {
                float hv = sH[(ty * 4 + r) * HH + kb * 64 + kk];
                hd[r] = pk2(hv, hv);
            }
#pragma unroll
            for (int q = 0; q < 2; q++) {
                ulonglong2 w = ((const ulonglong2*)sW)[kk * (HH / 4) + q * 16 + tx];
#pragma unroll
                for (int r = 0; r < 4; r++) {
                    accp3[r][q * 2 + 0] = f2fma(hd[r], w.x, accp3[r][q * 2 + 0]);
                    accp3[r][q * 2 + 1] = f2fma(hd[r], w.y, accp3[r][q * 2 + 1]);
                }
            }
        }
    }
    // write K into sA (64 x 128); sA is dead during GEMM3
#pragma unroll
    for (int q = 0; q < 2; q++)
#pragma unroll
        for (int h = 0; h < 2; h++) {
            int c = q * 64 + tx * 4 + h * 2;
#pragma unroll
            for (int r = 0; r < 4; r++) {
                float lo, hi; upk2(accp3[r][q * 2 + h], lo, hi);
                sA[(ty * 4 + r) * HH + c]     = lo;
                sA[(ty * 4 + r) * HH + c + 1] = hi;
            }
        }
    __syncthreads();

    // per-token norms: write norm_eff to global, 1/norm_eff to smem
    {
        int warp = tid >> 5, lane = tid & 31;
        for (int tt = warp * 8; tt < warp * 8 + 8; tt++) {
            float4 x = ((const float4*)sA)[tt * 32 + lane];
            float ss = fmaf(x.x, x.x, fmaf(x.y, x.y, fmaf(x.z, x.z, x.w * x.w)));
#pragma unroll
            for (int o = 16; o; o >>= 1) ss += __shfl_xor_sync(0xffffffffu, ss, o);
            if (lane == 0) {
                float n = fmaxf(sqrtf(ss), 1e-12f);
                g_nrm[t0 + tt] = n;
                sInv[tt] = 1.f / n;
            }
        }
    }
    __syncthreads();

    // write NORMALIZED kn to global: kn = k * (1/norm_eff)
    {
        float4* gk = (float4*)g_k;
        const float4* s = (const float4*)sA;
        for (int idx = tid; idx < TOK * 32; idx += 256) {
            float inv = sInv[idx >> 5];
            float4 v = s[idx];
            v.x *= inv; v.y *= inv; v.z *= inv; v.w *= inv;
            gk[(size_t)t0 * 32 + idx] = v;
        }
    }
}

// ---------------------------------------------------------------------------
// Kernel B: delta-rule scan. One warp = one (batch,row), 4096 warps (full
// occupancy hides L2 latency). Packed f32x2 dot/update + 5-SHFL butterfly.
// ---------------------------------------------------------------------------
__global__ void __launch_bounds__(256) kScan()
{
    const int warp = threadIdx.x >> 5, lane = threadIdx.x & 31;
    const int b = blockIdx.x >> 4;
    const int i = ((blockIdx.x & 15) << 3) + warp;

    const float*      kbase = g_k + (size_t)b * LL * HH;
    const ulonglong2* kp    = (const ulonglong2*)kbase + lane;  // 4 floats/lane, +32/step
    const float*      np    = g_nrm + b * LL;
    const float*      kip   = kbase + i;                        // kn[t][i] scalar

    ull m01 = 0ULL, m23 = 0ULL;

    // prologue: load step 0
    ulonglong2 cur = __ldg(kp);
    float kni = __ldg(kip);
    float nrm = __ldg(np);

    for (int t = 0; t < LL - 1; t++) {
        // prefetch t+1 (last prefetch = q row)
        ulonglong2 nxt = __ldg(&kp[(size_t)(t + 1) * 32]);
        float kni_n = __ldg(&kip[(size_t)(t + 1) * HH]);
        float nrm_n = __ldg(&np[t + 1]);

        // packed partial dot over this lane's 4 elements
        ull d = f2fma(m01, cur.x, 0ULL);
        d = f2fma(m23, cur.y, d);
        float lo, hi; upk2(d, lo, hi);
        float p = wredux(lo + hi);

        float c = fmaf(kni, nrm, -p);    // raw k_i - (M.kn)_i
        ull cd = pk2(c, c);
        m01 = f2fma(cd, cur.x, m01);
        m23 = f2fma(cd, cur.y, m23);

        cur = nxt; kni = kni_n; nrm = nrm_n;
    }

    // epilogue: q = kn[L-1] * nrm[L-1]  ->  read_i = nrm * (M . kn)
    ull d = f2fma(m01, cur.x, 0ULL);
    d = f2fma(m23, cur.y, d);
    float lo, hi; upk2(d, lo, hi);
    float p = wredux(lo + hi);
    if (lane == 0) g_read[b * HH + i] = p * nrm;
}

// ---------------------------------------------------------------------------
// Kernel C: r2 = read @ Wrp + brp   (32 x 128)
// ---------------------------------------------------------------------------
__global__ void __launch_bounds__(256) kC(const float* __restrict__ Wrp,
                                          const float* __restrict__ brp)
{
    int idx = blockIdx.x * 256 + threadIdx.x;
    if (idx >= BB * HH) return;
    int b = idx >> 7, d = idx & 127;
    float s = brp[d];
#pragma unroll 8
    for (int h = 0; h < HH; h++)
        s = fmaf(__ldg(&g_read[b * HH + h]), __ldg(&Wrp[h * HH + d]), s);
    g_r2[idx] = s;
}

// ---------------------------------------------------------------------------
// Kernel D: out = r2 @ Wout + bout   (32 x 32000). Thread per output column v,
// h-loop unrolled by 8 for MLP.
// ---------------------------------------------------------------------------
__global__ void __launch_bounds__(256) kD(const float* __restrict__ Wout,
                                          const float* __restrict__ bout,
                                          float* __restrict__ out)
{
    __shared__ float sr[BB * HH];
    for (int idx = threadIdx.x; idx < BB * HH; idx += 256) sr[idx] = g_r2[idx];
    __syncthreads();
    int v = blockIdx.x * 256 + threadIdx.x;
    if (v >= VV) return;

    float acc[BB];
#pragma unroll
    for (int b = 0; b < BB; b++) acc[b] = 0.f;

#pragma unroll 1
    for (int h0 = 0; h0 < HH; h0 += 8) {
        float wv[8];
#pragma unroll
        for (int u = 0; u < 8; u++)
            wv[u] = __ldg(&Wout[(size_t)(h0 + u) * VV + v]);
#pragma unroll
        for (int u = 0; u < 8; u++)
#pragma unroll
            for (int b = 0; b < BB; b++)
                acc[b] = fmaf(sr[b * HH + h0 + u], wv[u], acc[b]);
    }
    float bo = __ldg(&bout[v]);
#pragma unroll
    for (int b = 0; b < BB; b++)
        out[(size_t)b * VV + v] = acc[b] + bo;
}

// ---------------------------------------------------------------------------
extern "C" void kernel_launch(void* const* d_in, const int* in_sizes, int n_in,
                              void* d_out, int out_size)
{
    const int*   seq   = (const int*)d_in[0];
    const float* embed = (const float*)d_in[1];
    const float* W1    = (const float*)d_in[2];
    const float* b1    = (const float*)d_in[3];
    const float* W2    = (const float*)d_in[4];
    const float* b2    = (const float*)d_in[5];
    const float* lng   = (const float*)d_in[6];
    const float* lnb   = (const float*)d_in[7];
    const float* Wkp   = (const float*)d_in[8];
    const float* Wrp   = (const float*)d_in[9];
    const float* brp   = (const float*)d_in[10];
    const float* Wout  = (const float*)d_in[11];
    const float* bout  = (const float*)d_in[12];
    float* out = (float*)d_out;

    cudaFuncSetAttribute(kA, cudaFuncAttributeMaxDynamicSharedMemorySize, 131072);

    kA<<<NTOK / TOK, 256, 131072>>>(seq, embed, W1, b1, W2, b2, lng, lnb, Wkp);
    kScan<<<(BB * HH) / 8, 256>>>();
    kC<<<(BB * HH + 255) / 256, 256>>>(Wrp, brp);
    kD<<<(VV + 255) / 256, 256>>>(Wout, bout, out);
}